// round 3
// baseline (speedup 1.0000x reference)
#include <cuda_runtime.h>
#include <cuda_bf16.h>
#include <mma.h>

using namespace nvcuda;

#define CDIM   128
#define HEADS  4
#define HD     32
#define NTOK   49
#define NPAD   64
#define NWIN   64
#define NBLK   4096
#define NTHR   512

constexpr int LDX  = 132;   // row stride for 128-wide tiles (floats)
constexpr int LDSS = 68;    // row stride for 64-wide score tiles (floats)

// ---- shared memory layout (floats) ----
constexpr int OFF_X = 0;                       // 64 x 132   = 8448
constexpr int OFF_W = 8448;                    // 128 x 132  = 16896
constexpr int OFF_Q = 25344;                   // 64 x 132
constexpr int OFF_K = 33792;                   // 64 x 132
constexpr int OFF_V = 42240;                   // 64 x 132
constexpr int SMEM_FLOATS = 50688;             // 202,752 bytes
// reused regions:
constexpr int OFF_S = 0;                       // 4 * 64 * 68 = 17408  (over X+W)
constexpr int OFF_O = OFF_Q;                   // ctx over Q
constexpr int OFF_Y = OFF_V;                   // final tile over V

template <class Frag>
__device__ __forceinline__ void to_tf32(Frag& f) {
    #pragma unroll
    for (int t = 0; t < f.num_elements; t++) f.x[t] = wmma::__float_to_tf32(f.x[t]);
}

// load a 49x128 window (contiguous) into 64x132 smem tile, zero-padding rows 49..63
__device__ __forceinline__ void load_x(const float* __restrict__ src, float* sX, int tid) {
    #pragma unroll
    for (int i = tid; i < (NPAD * CDIM) / 4; i += NTHR) {
        int r = (i * 4) >> 7, c = (i * 4) & 127;
        float4 val = (r < NTOK) ? reinterpret_cast<const float4*>(src)[i]
                                : make_float4(0.f, 0.f, 0.f, 0.f);
        *reinterpret_cast<float4*>(&sX[r * LDX + c]) = val;
    }
}

// load 128x128 weight into 128x132 smem tile
__device__ __forceinline__ void load_w(const float* __restrict__ W, float* sW, int tid) {
    #pragma unroll
    for (int i = tid; i < (CDIM * CDIM) / 4; i += NTHR) {
        int r = (i * 4) >> 7, c = (i * 4) & 127;
        *reinterpret_cast<float4*>(&sW[r * LDX + c]) = reinterpret_cast<const float4*>(W)[i];
    }
}

// C[64,128] = A[64,128] @ B^T   (16 warps: 4 m-tiles x 4 n-tiles of 16x32)
__device__ __forceinline__ void gemm_proj(const float* sA, const float* sB, float* sC, int warp) {
    const int wm = (warp & 3) * 16;
    const int wn = (warp >> 2) * 32;

    wmma::fragment<wmma::accumulator, 16, 16, 8, float> acc[2];
    #pragma unroll
    for (int ni = 0; ni < 2; ni++) wmma::fill_fragment(acc[ni], 0.f);

    #pragma unroll 4
    for (int kk = 0; kk < CDIM; kk += 8) {
        wmma::fragment<wmma::matrix_a, 16, 16, 8, wmma::precision::tf32, wmma::row_major> a;
        wmma::fragment<wmma::matrix_b, 16, 16, 8, wmma::precision::tf32, wmma::col_major> b[2];
        wmma::load_matrix_sync(a, sA + wm * LDX + kk, LDX);
        to_tf32(a);
        #pragma unroll
        for (int ni = 0; ni < 2; ni++) {
            wmma::load_matrix_sync(b[ni], sB + (wn + ni * 16) * LDX + kk, LDX);
            to_tf32(b[ni]);
            wmma::mma_sync(acc[ni], a, b[ni], acc[ni]);
        }
    }
    #pragma unroll
    for (int ni = 0; ni < 2; ni++)
        wmma::store_matrix_sync(sC + wm * LDX + wn + ni * 16, acc[ni], LDX, wmma::mem_row_major);
}

__device__ __forceinline__ void bias_pass(float* sC, const float* __restrict__ bias, int tid) {
    #pragma unroll
    for (int i = tid; i < (NPAD * CDIM) / 4; i += NTHR) {
        int r = (i * 4) >> 7, c = (i * 4) & 127;
        float4 v = *reinterpret_cast<float4*>(&sC[r * LDX + c]);
        float4 b = *reinterpret_cast<const float4*>(&bias[c]);
        v.x += b.x; v.y += b.y; v.z += b.z; v.w += b.w;
        *reinterpret_cast<float4*>(&sC[r * LDX + c]) = v;
    }
}

__global__ void __launch_bounds__(NTHR, 1)
fused_wmca_kernel(const float* __restrict__ q_in, const float* __restrict__ k_in,
                  const float* __restrict__ v_in, const float* __restrict__ mask,
                  const float* __restrict__ Wq, const float* __restrict__ bq,
                  const float* __restrict__ Wk, const float* __restrict__ bk,
                  const float* __restrict__ Wv, const float* __restrict__ bv,
                  const float* __restrict__ Wo, const float* __restrict__ bo,
                  const float* __restrict__ rpb, const int* __restrict__ relidx,
                  float* __restrict__ out) {
    extern __shared__ float sm[];
    const int tid = threadIdx.x;
    const int warp = tid >> 5;
    const int w = blockIdx.x;
    const long base = (long)w * NTOK * CDIM;

    // ---------------- Q projection ----------------
    load_x(q_in + base, sm + OFF_X, tid);
    load_w(Wq, sm + OFF_W, tid);
    __syncthreads();
    gemm_proj(sm + OFF_X, sm + OFF_W, sm + OFF_Q, warp);
    __syncthreads();
    bias_pass(sm + OFF_Q, bq, tid);

    // ---------------- K projection ----------------
    load_x(k_in + base, sm + OFF_X, tid);
    load_w(Wk, sm + OFF_W, tid);
    __syncthreads();
    gemm_proj(sm + OFF_X, sm + OFF_W, sm + OFF_K, warp);
    __syncthreads();
    bias_pass(sm + OFF_K, bk, tid);

    // ---------------- V projection ----------------
    load_x(v_in + base, sm + OFF_X, tid);
    load_w(Wv, sm + OFF_W, tid);
    __syncthreads();
    gemm_proj(sm + OFF_X, sm + OFF_W, sm + OFF_V, warp);
    __syncthreads();
    bias_pass(sm + OFF_V, bv, tid);
    // Q/K bias completed before the V-stage syncs above; safe to read Q/K now.

    // ---------------- S = Q @ K^T per head (4 warps/head, 16 rows each) ----
    {
        const int h  = warp >> 2;
        const int mo = (warp & 3) * 16;
        wmma::fragment<wmma::accumulator, 16, 16, 8, float> acc[4];
        #pragma unroll
        for (int ni = 0; ni < 4; ni++) wmma::fill_fragment(acc[ni], 0.f);

        #pragma unroll
        for (int kk = 0; kk < HD; kk += 8) {
            wmma::fragment<wmma::matrix_a, 16, 16, 8, wmma::precision::tf32, wmma::row_major> a;
            wmma::fragment<wmma::matrix_b, 16, 16, 8, wmma::precision::tf32, wmma::col_major> b[4];
            wmma::load_matrix_sync(a, sm + OFF_Q + mo * LDX + h * HD + kk, LDX);
            to_tf32(a);
            #pragma unroll
            for (int ni = 0; ni < 4; ni++) {
                wmma::load_matrix_sync(b[ni], sm + OFF_K + (ni * 16) * LDX + h * HD + kk, LDX);
                to_tf32(b[ni]);
                wmma::mma_sync(acc[ni], a, b[ni], acc[ni]);
            }
        }
        #pragma unroll
        for (int ni = 0; ni < 4; ni++)
            wmma::store_matrix_sync(sm + OFF_S + h * NPAD * LDSS + mo * LDSS + ni * 16,
                                    acc[ni], LDSS, wmma::mem_row_major);
    }
    __syncthreads();

    // ---------------- scale + rpb bias + shift mask + softmax ----------------
    if (tid < HEADS * NTOK) {
        const int hh = tid / NTOK, i = tid % NTOK;
        float* row = sm + OFF_S + hh * NPAD * LDSS + i * LDSS;
        const float* mrow = mask + (long)(w & (NWIN - 1)) * NTOK * NTOK + i * NTOK;
        const int* rrow = relidx + i * NTOK;
        const float scale = 0.17677669529663687f;  // 32^-0.5
        float mx = -1e30f;
        #pragma unroll 7
        for (int j = 0; j < NTOK; j++) {
            float s = row[j] * scale + __ldg(&rpb[rrow[j] * HEADS + hh]) + mrow[j];
            row[j] = s;
            mx = fmaxf(mx, s);
        }
        float sum = 0.f;
        #pragma unroll 7
        for (int j = 0; j < NTOK; j++) { float e = __expf(row[j] - mx); row[j] = e; sum += e; }
        float inv = 1.f / sum;
        #pragma unroll 7
        for (int j = 0; j < NTOK; j++) row[j] *= inv;
        #pragma unroll
        for (int j = NTOK; j < NPAD; j++) row[j] = 0.f;   // kill padded K columns
    }
    __syncthreads();

    // ---------------- ctx = S @ V per head (4 warps/head, 16x32 each) -------
    {
        const int h  = warp >> 2;
        const int mo = (warp & 3) * 16;
        wmma::fragment<wmma::accumulator, 16, 16, 8, float> acc[2];
        #pragma unroll
        for (int ni = 0; ni < 2; ni++) wmma::fill_fragment(acc[ni], 0.f);

        #pragma unroll 4
        for (int kk = 0; kk < NPAD; kk += 8) {
            wmma::fragment<wmma::matrix_a, 16, 16, 8, wmma::precision::tf32, wmma::row_major> a;
            wmma::fragment<wmma::matrix_b, 16, 16, 8, wmma::precision::tf32, wmma::row_major> b[2];
            wmma::load_matrix_sync(a, sm + OFF_S + h * NPAD * LDSS + mo * LDSS + kk, LDSS);
            to_tf32(a);
            #pragma unroll
            for (int ni = 0; ni < 2; ni++) {
                wmma::load_matrix_sync(b[ni], sm + OFF_V + kk * LDX + h * HD + ni * 16, LDX);
                to_tf32(b[ni]);
                wmma::mma_sync(acc[ni], a, b[ni], acc[ni]);
            }
        }
        #pragma unroll
        for (int ni = 0; ni < 2; ni++)
            wmma::store_matrix_sync(sm + OFF_O + mo * LDX + h * HD + ni * 16,
                                    acc[ni], LDX, wmma::mem_row_major);
    }
    __syncthreads();

    // ---------------- output projection: Y = ctx @ Wo^T + bo ----------------
    load_w(Wo, sm + OFF_W, tid);   // over dead S region
    __syncthreads();
    gemm_proj(sm + OFF_O, sm + OFF_W, sm + OFF_Y, warp);
    __syncthreads();

    #pragma unroll
    for (int i = tid; i < (NTOK * CDIM) / 4; i += NTHR) {
        int r = (i * 4) >> 7, c = (i * 4) & 127;
        float4 v = *reinterpret_cast<float4*>(&sm[OFF_Y + r * LDX + c]);
        float4 b = *reinterpret_cast<const float4*>(&bo[c]);
        v.x += b.x; v.y += b.y; v.z += b.z; v.w += b.w;
        reinterpret_cast<float4*>(out + base)[i] = v;
    }
}

// ============================================================================
// launch
// ============================================================================
extern "C" void kernel_launch(void* const* d_in, const int* in_sizes, int n_in,
                              void* d_out, int out_size) {
    const float* q    = (const float*)d_in[0];
    const float* k    = (const float*)d_in[1];
    const float* v    = (const float*)d_in[2];
    const float* mask = (const float*)d_in[3];
    const float* Wq   = (const float*)d_in[4];
    const float* bq   = (const float*)d_in[5];
    const float* Wk   = (const float*)d_in[6];
    const float* bk   = (const float*)d_in[7];
    const float* Wv   = (const float*)d_in[8];
    const float* bv   = (const float*)d_in[9];
    const float* Wo   = (const float*)d_in[10];
    const float* bo   = (const float*)d_in[11];
    const float* rpb  = (const float*)d_in[12];
    const int*   ridx = (const int*)d_in[13];
    float* out = (float*)d_out;

    const size_t smem = (size_t)SMEM_FLOATS * sizeof(float);   // 202,752 B
    cudaFuncSetAttribute(fused_wmca_kernel, cudaFuncAttributeMaxDynamicSharedMemorySize, (int)smem);

    fused_wmca_kernel<<<NBLK, NTHR, smem>>>(q, k, v, mask, Wq, bq, Wk, bk, Wv, bv,
                                            Wo, bo, rpb, ridx, out);
}

// round 5
// speedup vs baseline: 1.8329x; 1.8329x over previous
#include <cuda_runtime.h>
#include <cuda_fp16.h>
#include <cstdint>
#include <mma.h>

using namespace nvcuda;

#define CDIM   128
#define HEADS  4
#define HD     32
#define NTOK   49
#define NPAD   64
#define NWIN   64
#define NBLK   4096
#define NTHR   512

constexpr int LDH  = 136;   // half-element stride for 128-wide half tiles (272B rows)
constexpr int LDC  = 132;   // float stride for fp32 staging tile
constexpr int LDS_ = 68;    // float stride for S score tiles
constexpr int LDP  = 72;    // half stride for P (probability) tiles

// ---- shared memory byte offsets ----
constexpr int OFF_XH = 0;            // 64  x 136 half = 17408 B
constexpr int OFF_WH = 17408;        // 128 x 136 half = 34816 B
constexpr int OFF_QH = 52224;        // 64 x 136 half
constexpr int OFF_KH = 69632;
constexpr int OFF_VH = 87040;
constexpr int OFF_S  = 104448;       // 4 x 64 x 68 fp32 = 69632 B
constexpr int OFF_C  = 104448;       // fp32 staging 64x132 (33792 B), aliases S
constexpr int OFF_P  = 174080;       // 4 x 64 x 72 half = 36864 B
constexpr int SMEM_BYTES = 210944;

// load 49x128 fp32 window -> 64x136 half tile (zero-pad rows 49..63)
__device__ __forceinline__ void load_xh(const float* __restrict__ src, __half* dst, int tid) {
    #pragma unroll
    for (int i = tid; i < (NPAD * CDIM) / 4; i += NTHR) {
        int r = (i * 4) >> 7, c = (i * 4) & 127;
        float4 v = (r < NTOK) ? reinterpret_cast<const float4*>(src)[i]
                              : make_float4(0.f, 0.f, 0.f, 0.f);
        __half2* d = reinterpret_cast<__half2*>(dst + r * LDH + c);
        d[0] = __floats2half2_rn(v.x, v.y);
        d[1] = __floats2half2_rn(v.z, v.w);
    }
}

// load 128x128 fp32 weight -> 128x136 half tile
__device__ __forceinline__ void load_wh(const float* __restrict__ W, __half* dst, int tid) {
    #pragma unroll
    for (int i = tid; i < (CDIM * CDIM) / 4; i += NTHR) {
        int r = (i * 4) >> 7, c = (i * 4) & 127;
        float4 v = reinterpret_cast<const float4*>(W)[i];
        __half2* d = reinterpret_cast<__half2*>(dst + r * LDH + c);
        d[0] = __floats2half2_rn(v.x, v.y);
        d[1] = __floats2half2_rn(v.z, v.w);
    }
}

// C[64,128] = A[64,128] @ B^T (half x half -> fp32), 16 warps: 4m x 4n of 16x32
__device__ __forceinline__ void gemm_proj_h(const __half* sA, const __half* sB,
                                            float* sC, int warp) {
    const int wm = (warp & 3) * 16;
    const int wn = (warp >> 2) * 32;

    wmma::fragment<wmma::accumulator, 16, 16, 16, float> acc[2];
    #pragma unroll
    for (int ni = 0; ni < 2; ni++) wmma::fill_fragment(acc[ni], 0.f);

    #pragma unroll
    for (int kk = 0; kk < CDIM; kk += 16) {
        wmma::fragment<wmma::matrix_a, 16, 16, 16, __half, wmma::row_major> a;
        wmma::fragment<wmma::matrix_b, 16, 16, 16, __half, wmma::col_major> b[2];
        wmma::load_matrix_sync(a, sA + wm * LDH + kk, LDH);
        #pragma unroll
        for (int ni = 0; ni < 2; ni++) {
            wmma::load_matrix_sync(b[ni], sB + (wn + ni * 16) * LDH + kk, LDH);
            wmma::mma_sync(acc[ni], a, b[ni], acc[ni]);
        }
    }
    #pragma unroll
    for (int ni = 0; ni < 2; ni++)
        wmma::store_matrix_sync(sC + wm * LDC + wn + ni * 16, acc[ni], LDC, wmma::mem_row_major);
}

// bias add (fp32 staging) then convert to half tile
__device__ __forceinline__ void bias_cvt(const float* sC, const float* __restrict__ bias,
                                         __half* dst, int tid) {
    #pragma unroll
    for (int i = tid; i < (NPAD * CDIM) / 4; i += NTHR) {
        int r = (i * 4) >> 7, c = (i * 4) & 127;
        float4 v = *reinterpret_cast<const float4*>(&sC[r * LDC + c]);
        float4 b = *reinterpret_cast<const float4*>(&bias[c]);
        __half2* d = reinterpret_cast<__half2*>(dst + r * LDH + c);
        d[0] = __floats2half2_rn(v.x + b.x, v.y + b.y);
        d[1] = __floats2half2_rn(v.z + b.z, v.w + b.w);
    }
}

__global__ void __launch_bounds__(NTHR, 1)
fused_wmca_kernel(const float* __restrict__ q_in, const float* __restrict__ k_in,
                  const float* __restrict__ v_in, const float* __restrict__ mask,
                  const float* __restrict__ Wq, const float* __restrict__ bq,
                  const float* __restrict__ Wk, const float* __restrict__ bk,
                  const float* __restrict__ Wv, const float* __restrict__ bv,
                  const float* __restrict__ Wo, const float* __restrict__ bo,
                  const float* __restrict__ rpb, const int* __restrict__ relidx,
                  float* __restrict__ out) {
    extern __shared__ char smraw[];
    __half* sXh = reinterpret_cast<__half*>(smraw + OFF_XH);
    __half* sWh = reinterpret_cast<__half*>(smraw + OFF_WH);
    __half* sQh = reinterpret_cast<__half*>(smraw + OFF_QH);
    __half* sKh = reinterpret_cast<__half*>(smraw + OFF_KH);
    __half* sVh = reinterpret_cast<__half*>(smraw + OFF_VH);
    float*  sS  = reinterpret_cast<float*>(smraw + OFF_S);
    float*  sC  = reinterpret_cast<float*>(smraw + OFF_C);
    __half* sP  = reinterpret_cast<__half*>(smraw + OFF_P);

    const int tid = threadIdx.x;
    const int warp = tid >> 5;
    const int w = blockIdx.x;
    const long base = (long)w * NTOK * CDIM;

    // ---------------- Q projection ----------------
    load_xh(q_in + base, sXh, tid);
    load_wh(Wq, sWh, tid);
    __syncthreads();
    gemm_proj_h(sXh, sWh, sC, warp);
    __syncthreads();
    bias_cvt(sC, bq, sQh, tid);

    // ---------------- K projection ----------------
    load_xh(k_in + base, sXh, tid);
    load_wh(Wk, sWh, tid);
    __syncthreads();                       // also orders bias_cvt(Q) before gemm's sC stores
    gemm_proj_h(sXh, sWh, sC, warp);
    __syncthreads();
    bias_cvt(sC, bk, sKh, tid);

    // ---------------- V projection ----------------
    load_xh(v_in + base, sXh, tid);
    load_wh(Wv, sWh, tid);
    __syncthreads();
    gemm_proj_h(sXh, sWh, sC, warp);
    __syncthreads();
    bias_cvt(sC, bv, sVh, tid);
    load_wh(Wo, sWh, tid);                 // prefetch Wo; overlaps with attention below
    __syncthreads();                       // bias_cvt(V) reads sC done before QK stores S

    // ---------------- S = Q @ K^T per head (4 warps/head, 16 rows each) ----
    {
        const int h  = warp >> 2;
        const int mo = (warp & 3) * 16;
        wmma::fragment<wmma::accumulator, 16, 16, 16, float> acc[4];
        #pragma unroll
        for (int ni = 0; ni < 4; ni++) wmma::fill_fragment(acc[ni], 0.f);

        #pragma unroll
        for (int kk = 0; kk < HD; kk += 16) {
            wmma::fragment<wmma::matrix_a, 16, 16, 16, __half, wmma::row_major> a;
            wmma::fragment<wmma::matrix_b, 16, 16, 16, __half, wmma::col_major> b[4];
            wmma::load_matrix_sync(a, sQh + mo * LDH + h * HD + kk, LDH);
            #pragma unroll
            for (int ni = 0; ni < 4; ni++) {
                wmma::load_matrix_sync(b[ni], sKh + (ni * 16) * LDH + h * HD + kk, LDH);
                wmma::mma_sync(acc[ni], a, b[ni], acc[ni]);
            }
        }
        #pragma unroll
        for (int ni = 0; ni < 4; ni++)
            wmma::store_matrix_sync(sS + h * NPAD * LDS_ + mo * LDS_ + ni * 16,
                                    acc[ni], LDS_, wmma::mem_row_major);
    }
    __syncthreads();

    // ------- scale + rpb bias + shift mask + softmax -> P (half) -------
    if (tid < HEADS * NTOK) {
        const int hh = tid / NTOK, i = tid % NTOK;
        const float* row = sS + hh * NPAD * LDS_ + i * LDS_;
        __half* prow = sP + hh * NPAD * LDP + i * LDP;
        const float* mrow = mask + (long)(w & (NWIN - 1)) * NTOK * NTOK + i * NTOK;
        const int* rrow = relidx + i * NTOK;
        const float scale = 0.17677669529663687f;  // 32^-0.5
        float sv[NTOK];
        float mx = -1e30f;
        #pragma unroll 7
        for (int j = 0; j < NTOK; j++) {
            float s = row[j] * scale + __ldg(&rpb[rrow[j] * HEADS + hh]) + mrow[j];
            sv[j] = s;
            mx = fmaxf(mx, s);
        }
        float sum = 0.f;
        #pragma unroll 7
        for (int j = 0; j < NTOK; j++) { float e = __expf(sv[j] - mx); sv[j] = e; sum += e; }
        float inv = 1.f / sum;
        #pragma unroll 7
        for (int j = 0; j < NTOK; j++) prow[j] = __float2half_rn(sv[j] * inv);
        #pragma unroll
        for (int j = NTOK; j < NPAD; j++) prow[j] = __float2half_rn(0.f);
    } else if (tid >= 256) {
        // zero padded P rows 49..63 (their AV results are discarded, but keep them finite)
        unsigned int* p32 = reinterpret_cast<unsigned int*>(sP);
        for (int i = tid - 256; i < HEADS * 15 * (LDP / 2); i += 256) {
            int hr = i / (LDP / 2), c = i % (LDP / 2);
            int h = hr / 15, r = 49 + hr % 15;
            p32[(h * NPAD * LDP + r * LDP) / 2 + c] = 0u;
        }
    }
    __syncthreads();

    // ---------------- ctx = P @ V per head -> fp32 staging ----------------
    {
        const int h  = warp >> 2;
        const int mo = (warp & 3) * 16;
        wmma::fragment<wmma::accumulator, 16, 16, 16, float> acc[2];
        #pragma unroll
        for (int ni = 0; ni < 2; ni++) wmma::fill_fragment(acc[ni], 0.f);

        #pragma unroll
        for (int kk = 0; kk < NPAD; kk += 16) {
            wmma::fragment<wmma::matrix_a, 16, 16, 16, __half, wmma::row_major> a;
            wmma::fragment<wmma::matrix_b, 16, 16, 16, __half, wmma::row_major> b[2];
            wmma::load_matrix_sync(a, sP + h * NPAD * LDP + mo * LDP + kk, LDP);
            #pragma unroll
            for (int ni = 0; ni < 2; ni++) {
                wmma::load_matrix_sync(b[ni], sVh + kk * LDH + h * HD + ni * 16, LDH);
                wmma::mma_sync(acc[ni], a, b[ni], acc[ni]);
            }
        }
        #pragma unroll
        for (int ni = 0; ni < 2; ni++)
            wmma::store_matrix_sync(sC + mo * LDC + h * HD + ni * 16,
                                    acc[ni], LDC, wmma::mem_row_major);
    }
    __syncthreads();

    // ctx fp32 -> half (over Xh region)
    #pragma unroll
    for (int i = tid; i < (NPAD * CDIM) / 4; i += NTHR) {
        int r = (i * 4) >> 7, c = (i * 4) & 127;
        float4 v = *reinterpret_cast<float4*>(&sC[r * LDC + c]);
        __half2* d = reinterpret_cast<__half2*>(sXh + r * LDH + c);
        d[0] = __floats2half2_rn(v.x, v.y);
        d[1] = __floats2half2_rn(v.z, v.w);
    }
    __syncthreads();

    // ---------------- output projection: Y = ctx @ Wo^T + bo ----------------
    gemm_proj_h(sXh, sWh, sC, warp);
    __syncthreads();

    #pragma unroll
    for (int i = tid; i < (NTOK * CDIM) / 4; i += NTHR) {
        int r = (i * 4) >> 7, c = (i * 4) & 127;
        float4 v = *reinterpret_cast<float4*>(&sC[r * LDC + c]);
        float4 b = *reinterpret_cast<const float4*>(&bo[c]);
        v.x += b.x; v.y += b.y; v.z += b.z; v.w += b.w;
        reinterpret_cast<float4*>(out + base)[i] = v;
    }
}

// ============================================================================
// launch
// ============================================================================
extern "C" void kernel_launch(void* const* d_in, const int* in_sizes, int n_in,
                              void* d_out, int out_size) {
    const float* q    = (const float*)d_in[0];
    const float* k    = (const float*)d_in[1];
    const float* v    = (const float*)d_in[2];
    const float* mask = (const float*)d_in[3];
    const float* Wq   = (const float*)d_in[4];
    const float* bq   = (const float*)d_in[5];
    const float* Wk   = (const float*)d_in[6];
    const float* bk   = (const float*)d_in[7];
    const float* Wv   = (const float*)d_in[8];
    const float* bv   = (const float*)d_in[9];
    const float* Wo   = (const float*)d_in[10];
    const float* bo   = (const float*)d_in[11];
    const float* rpb  = (const float*)d_in[12];
    const int*   ridx = (const int*)d_in[13];
    float* out = (float*)d_out;

    cudaFuncSetAttribute(fused_wmca_kernel, cudaFuncAttributeMaxDynamicSharedMemorySize,
                         SMEM_BYTES);

    fused_wmca_kernel<<<NBLK, NTHR, SMEM_BYTES>>>(q, k, v, mask, Wq, bq, Wk, bk, Wv, bv,
                                                  Wo, bo, rpb, ridx, out);
}

// round 6
// speedup vs baseline: 1.9126x; 1.0435x over previous
#include <cuda_runtime.h>
#include <cuda_fp16.h>
#include <cstdint>
#include <mma.h>

using namespace nvcuda;

#define CDIM   128
#define HEADS  4
#define HD     32
#define NTOK   49
#define NPAD   64
#define NWIN   64
#define NBLK   4096
#define NTHR   512

constexpr int KAUG = 144;   // 128 + 16 augmented K (bias fold)
constexpr int LDHA = 152;   // half stride for augmented tiles (304B rows, 16B-mult)
constexpr int LDH  = 136;   // half stride for 128-wide Q/K/V tiles
constexpr int LDC  = 132;   // float stride for final fp32 staging
constexpr int LDS_ = 68;    // float stride for S score tiles
constexpr int LDP  = 72;    // half stride for P tiles

// ---- shared memory byte offsets ----
constexpr int OFF_XA = 0;                     // 64  x 152 half = 19456  (X aug / ctx aug)
constexpr int OFF_WA = 19456;                 // 128 x 152 half = 38912
constexpr int OFF_QH = 58368;                 // 64 x 136 half  = 17408
constexpr int OFF_KH = 75776;
constexpr int OFF_VH = 93184;
constexpr int OFF_S  = 110592;                // 4 x 64 x 68 fp32 = 69632
constexpr int OFF_C  = OFF_S;                 // final fp32 staging 64x132 (33792), aliases S
constexpr int OFF_P  = 180224;                // 4 x 64 x 72 half = 36864
constexpr int SMEM_BYTES = 217088;

// 49x128 fp32 window -> 64x152 half aug tile: cols0-127 data, col128=1, 129-151=0, pad rows 0
__device__ __forceinline__ void load_x_aug(const float* __restrict__ src, __half* dst, int tid) {
    #pragma unroll
    for (int i = tid; i < (NPAD * CDIM) / 4; i += NTHR) {
        int r = (i * 4) >> 7, c = (i * 4) & 127;
        float4 v = (r < NTOK) ? reinterpret_cast<const float4*>(src)[i]
                              : make_float4(0.f, 0.f, 0.f, 0.f);
        __half2* d = reinterpret_cast<__half2*>(dst + r * LDHA + c);
        d[0] = __floats2half2_rn(v.x, v.y);
        d[1] = __floats2half2_rn(v.z, v.w);
    }
    if (tid < NPAD) {   // aug columns for row tid
        __half2* d = reinterpret_cast<__half2*>(dst + tid * LDHA + 128);
        d[0] = __floats2half2_rn(1.f, 0.f);
        #pragma unroll
        for (int j = 1; j < 12; j++) d[j] = __floats2half2_rn(0.f, 0.f);
    }
}

// 128x128 fp32 weight + bias -> 128x152 half aug tile: col128=bias[j]
__device__ __forceinline__ void load_w_aug(const float* __restrict__ W,
                                           const float* __restrict__ bias,
                                           __half* dst, int tid) {
    #pragma unroll
    for (int i = tid; i < (CDIM * CDIM) / 4; i += NTHR) {
        int r = (i * 4) >> 7, c = (i * 4) & 127;
        float4 v = reinterpret_cast<const float4*>(W)[i];
        __half2* d = reinterpret_cast<__half2*>(dst + r * LDHA + c);
        d[0] = __floats2half2_rn(v.x, v.y);
        d[1] = __floats2half2_rn(v.z, v.w);
    }
    if (tid < CDIM) {
        __half2* d = reinterpret_cast<__half2*>(dst + tid * LDHA + 128);
        d[0] = __floats2half2_rn(bias[tid], 0.f);
        #pragma unroll
        for (int j = 1; j < 12; j++) d[j] = __floats2half2_rn(0.f, 0.f);
    }
}

// C[64,128] = Aaug[64,144] @ Baug^T -> half dst (bias folded in K-aug)
__device__ __forceinline__ void gemm_aug_h(const __half* sA, const __half* sB,
                                           __half* dst, int warp) {
    const int wm = (warp & 3) * 16;
    const int wn = (warp >> 2) * 32;

    wmma::fragment<wmma::accumulator, 16, 16, 16, float> acc[2];
    #pragma unroll
    for (int ni = 0; ni < 2; ni++) wmma::fill_fragment(acc[ni], 0.f);

    #pragma unroll
    for (int kk = 0; kk < KAUG; kk += 16) {
        wmma::fragment<wmma::matrix_a, 16, 16, 16, __half, wmma::row_major> a;
        wmma::fragment<wmma::matrix_b, 16, 16, 16, __half, wmma::col_major> b[2];
        wmma::load_matrix_sync(a, sA + wm * LDHA + kk, LDHA);
        #pragma unroll
        for (int ni = 0; ni < 2; ni++) {
            wmma::load_matrix_sync(b[ni], sB + (wn + ni * 16) * LDHA + kk, LDHA);
            wmma::mma_sync(acc[ni], a, b[ni], acc[ni]);
        }
    }
    #pragma unroll
    for (int ni = 0; ni < 2; ni++) {
        wmma::fragment<wmma::accumulator, 16, 16, 16, __half> hacc;
        #pragma unroll
        for (int t = 0; t < hacc.num_elements; t++)
            hacc.x[t] = __float2half_rn(acc[ni].x[t]);
        wmma::store_matrix_sync(dst + wm * LDH + wn + ni * 16, hacc, LDH, wmma::mem_row_major);
    }
}

// same GEMM but fp32 output (final projection)
__device__ __forceinline__ void gemm_aug_f(const __half* sA, const __half* sB,
                                           float* sC, int warp) {
    const int wm = (warp & 3) * 16;
    const int wn = (warp >> 2) * 32;

    wmma::fragment<wmma::accumulator, 16, 16, 16, float> acc[2];
    #pragma unroll
    for (int ni = 0; ni < 2; ni++) wmma::fill_fragment(acc[ni], 0.f);

    #pragma unroll
    for (int kk = 0; kk < KAUG; kk += 16) {
        wmma::fragment<wmma::matrix_a, 16, 16, 16, __half, wmma::row_major> a;
        wmma::fragment<wmma::matrix_b, 16, 16, 16, __half, wmma::col_major> b[2];
        wmma::load_matrix_sync(a, sA + wm * LDHA + kk, LDHA);
        #pragma unroll
        for (int ni = 0; ni < 2; ni++) {
            wmma::load_matrix_sync(b[ni], sB + (wn + ni * 16) * LDHA + kk, LDHA);
            wmma::mma_sync(acc[ni], a, b[ni], acc[ni]);
        }
    }
    #pragma unroll
    for (int ni = 0; ni < 2; ni++)
        wmma::store_matrix_sync(sC + wm * LDC + wn + ni * 16, acc[ni], LDC, wmma::mem_row_major);
}

__global__ void __launch_bounds__(NTHR, 1)
fused_wmca_kernel(const float* __restrict__ q_in, const float* __restrict__ k_in,
                  const float* __restrict__ v_in, const float* __restrict__ mask,
                  const float* __restrict__ Wq, const float* __restrict__ bq,
                  const float* __restrict__ Wk, const float* __restrict__ bk,
                  const float* __restrict__ Wv, const float* __restrict__ bv,
                  const float* __restrict__ Wo, const float* __restrict__ bo,
                  const float* __restrict__ rpb, const int* __restrict__ relidx,
                  float* __restrict__ out) {
    extern __shared__ char smraw[];
    __half* sXA = reinterpret_cast<__half*>(smraw + OFF_XA);
    __half* sWA = reinterpret_cast<__half*>(smraw + OFF_WA);
    __half* sQh = reinterpret_cast<__half*>(smraw + OFF_QH);
    __half* sKh = reinterpret_cast<__half*>(smraw + OFF_KH);
    __half* sVh = reinterpret_cast<__half*>(smraw + OFF_VH);
    float*  sS  = reinterpret_cast<float*>(smraw + OFF_S);
    float*  sC  = reinterpret_cast<float*>(smraw + OFF_C);
    __half* sP  = reinterpret_cast<__half*>(smraw + OFF_P);

    const int tid = threadIdx.x;
    const int warp = tid >> 5;
    const int w = blockIdx.x;
    const long base = (long)w * NTOK * CDIM;

    // ---------------- Q projection (bias folded) ----------------
    load_x_aug(q_in + base, sXA, tid);
    load_w_aug(Wq, bq, sWA, tid);
    __syncthreads();
    gemm_aug_h(sXA, sWA, sQh, warp);
    __syncthreads();

    // ---------------- K projection ----------------
    load_x_aug(k_in + base, sXA, tid);
    load_w_aug(Wk, bk, sWA, tid);
    __syncthreads();
    gemm_aug_h(sXA, sWA, sKh, warp);
    __syncthreads();

    // ---------------- V projection ----------------
    load_x_aug(v_in + base, sXA, tid);
    load_w_aug(Wv, bv, sWA, tid);
    __syncthreads();
    gemm_aug_h(sXA, sWA, sVh, warp);
    __syncthreads();
    // NOTE: sXA cols 128..151 now hold [1,0,...] per row — reused as ctx augmentation.

    // ---------------- Wo prefetch + S = Q @ K^T per head ----------------
    load_w_aug(Wo, bo, sWA, tid);
    {
        const int h  = warp >> 2;
        const int mo = (warp & 3) * 16;
        wmma::fragment<wmma::accumulator, 16, 16, 16, float> acc[4];
        #pragma unroll
        for (int ni = 0; ni < 4; ni++) wmma::fill_fragment(acc[ni], 0.f);

        #pragma unroll
        for (int kk = 0; kk < HD; kk += 16) {
            wmma::fragment<wmma::matrix_a, 16, 16, 16, __half, wmma::row_major> a;
            wmma::fragment<wmma::matrix_b, 16, 16, 16, __half, wmma::col_major> b[4];
            wmma::load_matrix_sync(a, sQh + mo * LDH + h * HD + kk, LDH);
            #pragma unroll
            for (int ni = 0; ni < 4; ni++) {
                wmma::load_matrix_sync(b[ni], sKh + (ni * 16) * LDH + h * HD + kk, LDH);
                wmma::mma_sync(acc[ni], a, b[ni], acc[ni]);
            }
        }
        #pragma unroll
        for (int ni = 0; ni < 4; ni++)
            wmma::store_matrix_sync(sS + h * NPAD * LDS_ + mo * LDS_ + ni * 16,
                                    acc[ni], LDS_, wmma::mem_row_major);
    }
    __syncthreads();

    // ------- scale + rpb bias + shift mask + softmax -> P (half) -------
    if (tid < HEADS * NTOK) {
        const int hh = tid / NTOK, i = tid % NTOK;
        const float* row = sS + hh * NPAD * LDS_ + i * LDS_;
        __half* prow = sP + hh * NPAD * LDP + i * LDP;
        const float* mrow = mask + (long)(w & (NWIN - 1)) * NTOK * NTOK + i * NTOK;
        const int* rrow = relidx + i * NTOK;
        const float scale = 0.17677669529663687f;  // 32^-0.5
        float sv[NTOK];
        float mx = -1e30f;
        #pragma unroll 7
        for (int j = 0; j < NTOK; j++) {
            float s = row[j] * scale + __ldg(&rpb[rrow[j] * HEADS + hh]) + mrow[j];
            sv[j] = s;
            mx = fmaxf(mx, s);
        }
        float sum = 0.f;
        #pragma unroll 7
        for (int j = 0; j < NTOK; j++) { float e = __expf(sv[j] - mx); sv[j] = e; sum += e; }
        float inv = 1.f / sum;
        #pragma unroll 7
        for (int j = 0; j < NTOK; j++) prow[j] = __float2half_rn(sv[j] * inv);
        #pragma unroll
        for (int j = NTOK; j < NPAD; j++) prow[j] = __float2half_rn(0.f);
    } else if (tid >= 256) {
        // zero padded P rows 49..63 (AV results for those rows are discarded)
        unsigned int* p32 = reinterpret_cast<unsigned int*>(sP);
        for (int i = tid - 256; i < HEADS * 15 * (LDP / 2); i += 256) {
            int hr = i / (LDP / 2), c = i % (LDP / 2);
            int h = hr / 15, r = 49 + hr % 15;
            p32[(h * NPAD * LDP + r * LDP) / 2 + c] = 0u;
        }
    }
    __syncthreads();

    // ------- ctx = P @ V per head -> half, written into sXA cols 0..127 -------
    {
        const int h  = warp >> 2;
        const int mo = (warp & 3) * 16;
        wmma::fragment<wmma::accumulator, 16, 16, 16, float> acc[2];
        #pragma unroll
        for (int ni = 0; ni < 2; ni++) wmma::fill_fragment(acc[ni], 0.f);

        #pragma unroll
        for (int kk = 0; kk < NPAD; kk += 16) {
            wmma::fragment<wmma::matrix_a, 16, 16, 16, __half, wmma::row_major> a;
            wmma::fragment<wmma::matrix_b, 16, 16, 16, __half, wmma::row_major> b[2];
            wmma::load_matrix_sync(a, sP + h * NPAD * LDP + mo * LDP + kk, LDP);
            #pragma unroll
            for (int ni = 0; ni < 2; ni++) {
                wmma::load_matrix_sync(b[ni], sVh + kk * LDH + h * HD + ni * 16, LDH);
                wmma::mma_sync(acc[ni], a, b[ni], acc[ni]);
            }
        }
        #pragma unroll
        for (int ni = 0; ni < 2; ni++) {
            wmma::fragment<wmma::accumulator, 16, 16, 16, __half> hacc;
            #pragma unroll
            for (int t = 0; t < hacc.num_elements; t++)
                hacc.x[t] = __float2half_rn(acc[ni].x[t]);
            wmma::store_matrix_sync(sXA + mo * LDHA + h * HD + ni * 16,
                                    hacc, LDHA, wmma::mem_row_major);
        }
    }
    __syncthreads();

    // ---------------- output projection: Y = ctx_aug @ WoAug^T (bias folded) ----
    gemm_aug_f(sXA, sWA, sC, warp);
    __syncthreads();

    #pragma unroll
    for (int i = tid; i < (NTOK * CDIM) / 4; i += NTHR) {
        int r = (i * 4) >> 7, c = (i * 4) & 127;
        reinterpret_cast<float4*>(out + base)[i] =
            *reinterpret_cast<float4*>(&sC[r * LDC + c]);
    }
}

// ============================================================================
// launch
// ============================================================================
extern "C" void kernel_launch(void* const* d_in, const int* in_sizes, int n_in,
                              void* d_out, int out_size) {
    const float* q    = (const float*)d_in[0];
    const float* k    = (const float*)d_in[1];
    const float* v    = (const float*)d_in[2];
    const float* mask = (const float*)d_in[3];
    const float* Wq   = (const float*)d_in[4];
    const float* bq   = (const float*)d_in[5];
    const float* Wk   = (const float*)d_in[6];
    const float* bk   = (const float*)d_in[7];
    const float* Wv   = (const float*)d_in[8];
    const float* bv   = (const float*)d_in[9];
    const float* Wo   = (const float*)d_in[10];
    const float* bo   = (const float*)d_in[11];
    const float* rpb  = (const float*)d_in[12];
    const int*   ridx = (const int*)d_in[13];
    float* out = (float*)d_out;

    cudaFuncSetAttribute(fused_wmca_kernel, cudaFuncAttributeMaxDynamicSharedMemorySize,
                         SMEM_BYTES);

    fused_wmca_kernel<<<NBLK, NTHR, SMEM_BYTES>>>(q, k, v, mask, Wq, bq, Wk, bk, Wv, bv,
                                                  Wo, bo, rpb, ridx, out);
}

// round 7
// speedup vs baseline: 2.1222x; 1.1096x over previous
#include <cuda_runtime.h>
#include <cuda_fp16.h>
#include <cstdint>
#include <mma.h>

using namespace nvcuda;

#define CDIM   128
#define HEADS  4
#define HD     32
#define NTOK   49
#define NPAD   64
#define NWIN   64
#define NBLK   2048   // 2 windows per CTA
#define NTHR   512

constexpr int KAUG = 144;   // 128 + 16 augmented K (bias fold)
constexpr int LDHA = 152;   // half stride, augmented tiles (304B rows)
constexpr int LDH  = 136;   // half stride, 128-wide tiles (272B rows)
constexpr int LDSf = 68;    // float stride, S tiles (272B rows)  == P stride 136 halves
constexpr int LDC  = 132;   // float stride, fp32 out staging

// ---- shared memory byte offsets ----
constexpr int OFF_XA  = 0;        // 128x152 half = 38912 | later: S (4x64x68 f32 = 69632 spans XA+WA) | later: WoA
constexpr int OFF_WA  = 38912;    // 128x152 half = 38912 | later: S tail | later: sC (128x132 f32 = 67584, spills into dead Q)
constexpr int OFF_S   = 0;
constexpr int OFF_C   = 38912;    // 38912 + 67584 = 106496 (over WA + dead Q region)
constexpr int OFF_Q   = 77824;    // 128x136 half = 34816
constexpr int OFF_K   = 112640;   // 128x136 half
constexpr int OFF_V   = 147456;   // 128x136 half
constexpr int OFF_CTX = 182272;   // 128x152 half = 38912 (dedicated)
constexpr int SMEM_BYTES = 221184;

// two 49x128 fp32 windows -> 128x152 half aug tile (rows 0-63: w0, 64-127: w1; aug=1 real rows only)
__device__ __forceinline__ void load_x2(const float* __restrict__ src, __half* dst, int tid) {
    #pragma unroll
    for (int i = tid; i < (128 * CDIM) / 4; i += NTHR) {
        int r = (i * 4) >> 7, c = (i * 4) & 127;
        int wi = r >> 6, rr = r & 63;
        float4 v = make_float4(0.f, 0.f, 0.f, 0.f);
        if (rr < NTOK)
            v = reinterpret_cast<const float4*>(src + (wi * NTOK + rr) * CDIM)[c >> 2];
        __half2* d = reinterpret_cast<__half2*>(dst + r * LDHA + c);
        d[0] = __floats2half2_rn(v.x, v.y);
        d[1] = __floats2half2_rn(v.z, v.w);
    }
    if (tid < 128) {
        int rr = tid & 63;
        __half2* d = reinterpret_cast<__half2*>(dst + tid * LDHA + 128);
        d[0] = __floats2half2_rn(rr < NTOK ? 1.f : 0.f, 0.f);
        #pragma unroll
        for (int j = 1; j < 12; j++) d[j] = __floats2half2_rn(0.f, 0.f);
    }
}

// 128x128 fp32 weight + bias -> 128x152 half aug tile (col128 = bias[j])
__device__ __forceinline__ void load_w_aug(const float* __restrict__ W,
                                           const float* __restrict__ bias,
                                           __half* dst, int tid) {
    #pragma unroll
    for (int i = tid; i < (CDIM * CDIM) / 4; i += NTHR) {
        int r = (i * 4) >> 7, c = (i * 4) & 127;
        float4 v = reinterpret_cast<const float4*>(W)[i];
        __half2* d = reinterpret_cast<__half2*>(dst + r * LDHA + c);
        d[0] = __floats2half2_rn(v.x, v.y);
        d[1] = __floats2half2_rn(v.z, v.w);
    }
    if (tid < CDIM) {
        __half2* d = reinterpret_cast<__half2*>(dst + tid * LDHA + 128);
        d[0] = __floats2half2_rn(bias[tid], 0.f);
        #pragma unroll
        for (int j = 1; j < 12; j++) d[j] = __floats2half2_rn(0.f, 0.f);
    }
}

// C[128,128] = Aaug[128,144] @ Baug^T -> half dst; 16 warps as 4m x 4n, each 32x32 (2m x 2n tiles)
__device__ __forceinline__ void gemm128_h(const __half* sA, const __half* sB,
                                          __half* dst, int warp) {
    const int wm = (warp & 3) * 32;
    const int wn = (warp >> 2) * 32;

    wmma::fragment<wmma::accumulator, 16, 16, 16, float> acc[2][2];
    #pragma unroll
    for (int mi = 0; mi < 2; mi++)
        #pragma unroll
        for (int ni = 0; ni < 2; ni++) wmma::fill_fragment(acc[mi][ni], 0.f);

    #pragma unroll
    for (int kk = 0; kk < KAUG; kk += 16) {
        wmma::fragment<wmma::matrix_a, 16, 16, 16, __half, wmma::row_major> a[2];
        wmma::fragment<wmma::matrix_b, 16, 16, 16, __half, wmma::col_major> b[2];
        #pragma unroll
        for (int mi = 0; mi < 2; mi++)
            wmma::load_matrix_sync(a[mi], sA + (wm + mi * 16) * LDHA + kk, LDHA);
        #pragma unroll
        for (int ni = 0; ni < 2; ni++) {
            wmma::load_matrix_sync(b[ni], sB + (wn + ni * 16) * LDHA + kk, LDHA);
            #pragma unroll
            for (int mi = 0; mi < 2; mi++)
                wmma::mma_sync(acc[mi][ni], a[mi], b[ni], acc[mi][ni]);
        }
    }
    #pragma unroll
    for (int mi = 0; mi < 2; mi++)
        #pragma unroll
        for (int ni = 0; ni < 2; ni++) {
            wmma::fragment<wmma::accumulator, 16, 16, 16, __half> hacc;
            #pragma unroll
            for (int t = 0; t < hacc.num_elements; t++)
                hacc.x[t] = __float2half_rn(acc[mi][ni].x[t]);
            wmma::store_matrix_sync(dst + (wm + mi * 16) * LDH + wn + ni * 16,
                                    hacc, LDH, wmma::mem_row_major);
        }
}

// same shape but fp32 output (final projection), A has LDHA stride
__device__ __forceinline__ void gemm128_f(const __half* sA, const __half* sB,
                                          float* sC, int warp) {
    const int wm = (warp & 3) * 32;
    const int wn = (warp >> 2) * 32;

    wmma::fragment<wmma::accumulator, 16, 16, 16, float> acc[2][2];
    #pragma unroll
    for (int mi = 0; mi < 2; mi++)
        #pragma unroll
        for (int ni = 0; ni < 2; ni++) wmma::fill_fragment(acc[mi][ni], 0.f);

    #pragma unroll
    for (int kk = 0; kk < KAUG; kk += 16) {
        wmma::fragment<wmma::matrix_a, 16, 16, 16, __half, wmma::row_major> a[2];
        wmma::fragment<wmma::matrix_b, 16, 16, 16, __half, wmma::col_major> b[2];
        #pragma unroll
        for (int mi = 0; mi < 2; mi++)
            wmma::load_matrix_sync(a[mi], sA + (wm + mi * 16) * LDHA + kk, LDHA);
        #pragma unroll
        for (int ni = 0; ni < 2; ni++) {
            wmma::load_matrix_sync(b[ni], sB + (wn + ni * 16) * LDHA + kk, LDHA);
            #pragma unroll
            for (int mi = 0; mi < 2; mi++)
                wmma::mma_sync(acc[mi][ni], a[mi], b[ni], acc[mi][ni]);
        }
    }
    #pragma unroll
    for (int mi = 0; mi < 2; mi++)
        #pragma unroll
        for (int ni = 0; ni < 2; ni++)
            wmma::store_matrix_sync(sC + (wm + mi * 16) * LDC + wn + ni * 16,
                                    acc[mi][ni], LDC, wmma::mem_row_major);
}

__global__ void __launch_bounds__(NTHR, 1)
fused_wmca_kernel(const float* __restrict__ q_in, const float* __restrict__ k_in,
                  const float* __restrict__ v_in, const float* __restrict__ mask,
                  const float* __restrict__ Wq, const float* __restrict__ bq,
                  const float* __restrict__ Wk, const float* __restrict__ bk,
                  const float* __restrict__ Wv, const float* __restrict__ bv,
                  const float* __restrict__ Wo, const float* __restrict__ bo,
                  const float* __restrict__ rpb, const int* __restrict__ relidx,
                  float* __restrict__ out) {
    extern __shared__ char smraw[];
    __half* sXA  = reinterpret_cast<__half*>(smraw + OFF_XA);
    __half* sWA  = reinterpret_cast<__half*>(smraw + OFF_WA);
    __half* sQh  = reinterpret_cast<__half*>(smraw + OFF_Q);
    __half* sKh  = reinterpret_cast<__half*>(smraw + OFF_K);
    __half* sVh  = reinterpret_cast<__half*>(smraw + OFF_V);
    __half* sCtx = reinterpret_cast<__half*>(smraw + OFF_CTX);
    float*  sS   = reinterpret_cast<float*>(smraw + OFF_S);
    __half* sP   = reinterpret_cast<__half*>(smraw + OFF_S);   // P aliases S rows in place
    float*  sC   = reinterpret_cast<float*>(smraw + OFF_C);

    const int tid = threadIdx.x;
    const int warp = tid >> 5;
    const long base = (long)blockIdx.x * 2 * NTOK * CDIM;

    // ---------------- Q projection (2 windows, bias folded) ----------------
    load_x2(q_in + base, sXA, tid);
    load_w_aug(Wq, bq, sWA, tid);
    // init ctx augmentation columns once (dedicated region, used at the end)
    if (tid < 128) {
        __half2* d = reinterpret_cast<__half2*>(sCtx + tid * LDHA + 128);
        d[0] = __floats2half2_rn(1.f, 0.f);
        #pragma unroll
        for (int j = 1; j < 12; j++) d[j] = __floats2half2_rn(0.f, 0.f);
    }
    __syncthreads();
    gemm128_h(sXA, sWA, sQh, warp);
    __syncthreads();

    // ---------------- K projection ----------------
    load_x2(k_in + base, sXA, tid);
    load_w_aug(Wk, bk, sWA, tid);
    __syncthreads();
    gemm128_h(sXA, sWA, sKh, warp);
    __syncthreads();

    // ---------------- V projection ----------------
    load_x2(v_in + base, sXA, tid);
    load_w_aug(Wv, bv, sWA, tid);
    __syncthreads();
    gemm128_h(sXA, sWA, sVh, warp);
    __syncthreads();
    // XA + WA now dead -> S region

    // ---------------- attention: two window passes ----------------
    #pragma unroll 1
    for (int wi = 0; wi < 2; wi++) {
        const __half* Qw = sQh + wi * 64 * LDH;
        const __half* Kw = sKh + wi * 64 * LDH;
        const __half* Vw = sVh + wi * 64 * LDH;

        // S = Q @ K^T per head (4 warps/head, 16 rows each)
        {
            const int h  = warp >> 2;
            const int mo = (warp & 3) * 16;
            wmma::fragment<wmma::accumulator, 16, 16, 16, float> acc[4];
            #pragma unroll
            for (int ni = 0; ni < 4; ni++) wmma::fill_fragment(acc[ni], 0.f);

            #pragma unroll
            for (int kk = 0; kk < HD; kk += 16) {
                wmma::fragment<wmma::matrix_a, 16, 16, 16, __half, wmma::row_major> a;
                wmma::fragment<wmma::matrix_b, 16, 16, 16, __half, wmma::col_major> b[4];
                wmma::load_matrix_sync(a, Qw + mo * LDH + h * HD + kk, LDH);
                #pragma unroll
                for (int ni = 0; ni < 4; ni++) {
                    wmma::load_matrix_sync(b[ni], Kw + (ni * 16) * LDH + h * HD + kk, LDH);
                    wmma::mma_sync(acc[ni], a, b[ni], acc[ni]);
                }
            }
            #pragma unroll
            for (int ni = 0; ni < 4; ni++)
                wmma::store_matrix_sync(sS + h * NPAD * LDSf + mo * LDSf + ni * 16,
                                        acc[ni], LDSf, wmma::mem_row_major);
        }
        __syncthreads();

        // softmax: S(fp32) row -> P(half) written in place over the same row bytes.
        // Padded rows 49..63 are exact zeros (aug=0 pad rows -> Q/K pad rows zero -> S zero,
        // and fp32 0 bits == two half zeros), so no pad pass needed.
        if (tid < HEADS * NTOK) {
            const int hh = tid / NTOK, i = tid % NTOK;
            const float* row = sS + hh * NPAD * LDSf + i * LDSf;
            __half* prow = sP + hh * NPAD * LDH + i * LDH;
            const int mw = (2 * blockIdx.x + wi) & (NWIN - 1);
            const float* mrow = mask + (long)mw * NTOK * NTOK + i * NTOK;
            const int* rrow = relidx + i * NTOK;
            const float scale = 0.17677669529663687f;  // 32^-0.5
            float sv[NTOK];
            float mx = -1e30f;
            #pragma unroll 7
            for (int j = 0; j < NTOK; j++) {
                float s = row[j] * scale + __ldg(&rpb[rrow[j] * HEADS + hh]) + mrow[j];
                sv[j] = s;
                mx = fmaxf(mx, s);
            }
            float sum = 0.f;
            #pragma unroll 7
            for (int j = 0; j < NTOK; j++) { float e = __expf(sv[j] - mx); sv[j] = e; sum += e; }
            float inv = 1.f / sum;
            #pragma unroll 7
            for (int j = 0; j < NTOK; j++) prow[j] = __float2half_rn(sv[j] * inv);
            #pragma unroll
            for (int j = NTOK; j < NPAD; j++) prow[j] = __float2half_rn(0.f);
        }
        __syncthreads();

        // ctx = P @ V per head -> half into ctx rows (wi*64 ..)
        {
            const int h  = warp >> 2;
            const int mo = (warp & 3) * 16;
            wmma::fragment<wmma::accumulator, 16, 16, 16, float> acc[2];
            #pragma unroll
            for (int ni = 0; ni < 2; ni++) wmma::fill_fragment(acc[ni], 0.f);

            #pragma unroll
            for (int kk = 0; kk < NPAD; kk += 16) {
                wmma::fragment<wmma::matrix_a, 16, 16, 16, __half, wmma::row_major> a;
                wmma::fragment<wmma::matrix_b, 16, 16, 16, __half, wmma::row_major> b[2];
                wmma::load_matrix_sync(a, sP + h * NPAD * LDH + mo * LDH + kk, LDH);
                #pragma unroll
                for (int ni = 0; ni < 2; ni++) {
                    wmma::load_matrix_sync(b[ni], Vw + kk * LDH + h * HD + ni * 16, LDH);
                    wmma::mma_sync(acc[ni], a, b[ni], acc[ni]);
                }
            }
            #pragma unroll
            for (int ni = 0; ni < 2; ni++) {
                wmma::fragment<wmma::accumulator, 16, 16, 16, __half> hacc;
                #pragma unroll
                for (int t = 0; t < hacc.num_elements; t++)
                    hacc.x[t] = __float2half_rn(acc[ni].x[t]);
                wmma::store_matrix_sync(sCtx + (wi * 64 + mo) * LDHA + h * HD + ni * 16,
                                        hacc, LDHA, wmma::mem_row_major);
            }
        }
        __syncthreads();
    }

    // ---------------- output projection: Y = ctx_aug @ WoAug^T ----------------
    load_w_aug(Wo, bo, sXA, tid);          // over dead S region (offset 0)
    __syncthreads();
    gemm128_f(sCtx, sXA, sC, warp);        // sC spans dead WA + dead Q regions
    __syncthreads();

    #pragma unroll
    for (int i = tid; i < (2 * NTOK * CDIM) / 4; i += NTHR) {
        int r = (i * 4) >> 7, c = (i * 4) & 127;          // r in 0..97
        int sr = (r < NTOK) ? r : (64 + r - NTOK);        // skip padded rows
        reinterpret_cast<float4*>(out + base)[i] =
            *reinterpret_cast<float4*>(&sC[sr * LDC + c]);
    }
}

// ============================================================================
// launch
// ============================================================================
extern "C" void kernel_launch(void* const* d_in, const int* in_sizes, int n_in,
                              void* d_out, int out_size) {
    const float* q    = (const float*)d_in[0];
    const float* k    = (const float*)d_in[1];
    const float* v    = (const float*)d_in[2];
    const float* mask = (const float*)d_in[3];
    const float* Wq   = (const float*)d_in[4];
    const float* bq   = (const float*)d_in[5];
    const float* Wk   = (const float*)d_in[6];
    const float* bk   = (const float*)d_in[7];
    const float* Wv   = (const float*)d_in[8];
    const float* bv   = (const float*)d_in[9];
    const float* Wo   = (const float*)d_in[10];
    const float* bo   = (const float*)d_in[11];
    const float* rpb  = (const float*)d_in[12];
    const int*   ridx = (const int*)d_in[13];
    float* out = (float*)d_out;

    cudaFuncSetAttribute(fused_wmca_kernel, cudaFuncAttributeMaxDynamicSharedMemorySize,
                         SMEM_BYTES);

    fused_wmca_kernel<<<NBLK, NTHR, SMEM_BYTES>>>(q, k, v, mask, Wq, bq, Wk, bk, Wv, bv,
                                                  Wo, bo, rpb, ridx, out);
}